// round 1
// baseline (speedup 1.0000x reference)
#include <cuda_runtime.h>
#include <math.h>

// Problem dims
constexpr int NB = 64;    // batch
constexpr int NT = 12;    // time steps / events
constexpr int ND = 256;   // D
constexpr int NS = 512;   // num symbols (2K)
constexpr int NV = 512;   // V
constexpr int GRAPH_STEPS = 3;

// Scratch (device globals: no allocation allowed)
__device__ float g_mg[NB * NT];
__device__ float g_sg[NB * NT];
__device__ float g_gs[NB * 2 * ND];

__device__ __forceinline__ float gelu_f(float x) {
    // exact-erf GELU (jax approximate=False)
    return 0.5f * x * (1.0f + erff(x * 0.70710678118654752440f));
}
__device__ __forceinline__ float sigmoid_f(float x) {
    return 1.0f / (1.0f + expf(-x));
}

// ---------------------------------------------------------------------------
// Kernel 1: per-(b,t) gate MLPs.  grid = NB blocks, 256 threads.
// Each block handles all 12 rows of one batch so Wmg1/Wsg1 are read once per
// block (weight reuse x12).
// ---------------------------------------------------------------------------
__global__ void gates_kernel(const float* __restrict__ evidence,
                             const float* __restrict__ Wmg1, const float* __restrict__ bmg1,
                             const float* __restrict__ Wmg2, const float* __restrict__ bmg2,
                             const float* __restrict__ Wsg1, const float* __restrict__ bsg1,
                             const float* __restrict__ Wsg2, const float* __restrict__ bsg2)
{
    __shared__ float x[NT][ND];          // 12 KB
    __shared__ float red[2 * NT][ND];    // 24 KB
    const int b = blockIdx.x;
    const int j = threadIdx.x;           // hidden unit / lane 0..255

    #pragma unroll
    for (int r = 0; r < NT; r++)
        x[r][j] = evidence[(b * NT + r) * ND + j];
    __syncthreads();

    float hm[NT], hs[NT];
    #pragma unroll
    for (int r = 0; r < NT; r++) { hm[r] = 0.f; hs[r] = 0.f; }

    for (int d = 0; d < ND; d++) {
        const float wm = Wmg1[d * ND + j];
        const float ws = Wsg1[d * ND + j];
        #pragma unroll
        for (int r = 0; r < NT; r++) {
            const float xv = x[r][d];
            hm[r] = fmaf(xv, wm, hm[r]);
            hs[r] = fmaf(xv, ws, hs[r]);
        }
    }

    const float w2m = Wmg2[j], w2s = Wsg2[j];
    const float b1m = bmg1[j], b1s = bsg1[j];
    #pragma unroll
    for (int r = 0; r < NT; r++) {
        red[r][j]      = gelu_f(hm[r] + b1m) * w2m;
        red[NT + r][j] = gelu_f(hs[r] + b1s) * w2s;
    }
    __syncthreads();

    // reduce all 24 rows simultaneously over j
    for (int off = 128; off > 0; off >>= 1) {
        if (j < off) {
            #pragma unroll
            for (int r = 0; r < 2 * NT; r++) red[r][j] += red[r][j + off];
        }
        __syncthreads();
    }
    if (j < NT) {
        g_mg[b * NT + j] = sigmoid_f(red[j][0]      + bmg2[0]);
        g_sg[b * NT + j] = sigmoid_f(red[NT + j][0] + bsg2[0]);
    }
}

// ---------------------------------------------------------------------------
// Kernel 2: sparse graph memory + readout.  grid = NB blocks, 256 threads.
// map_mem / step_mem are never materialized: each is <=12 (src,tgt,val)
// triples.  walk is a dense 512-float smem vector; hops are smem atomics.
// symbol_emb / value_emb are gathered only at nonzero support rows.
// ---------------------------------------------------------------------------
__global__ void graph_kernel(const int* __restrict__ em,  const int* __restrict__ si,
                             const int* __restrict__ sv,  const int* __restrict__ tsi,
                             const int* __restrict__ tsv, const int* __restrict__ tvi,
                             const int* __restrict__ tvv, const int* __restrict__ qi,
                             const int* __restrict__ qv,
                             const float* __restrict__ symbol_emb,
                             const float* __restrict__ value_emb)
{
    __shared__ float walk[NS], nwalk[NS], accv[NV];
    __shared__ int   e_msrc[NT], e_mtgt[NT], e_ssrc[NT], e_stgt[NT];
    __shared__ float e_mval[NT], e_sval[NT];

    const int b = blockIdx.x;
    const int tid = threadIdx.x;

    walk[tid] = 0.f;  walk[tid + 256] = 0.f;
    accv[tid] = 0.f;  accv[tid + 256] = 0.f;

    if (tid < NT) {
        const int t   = tid;
        const int mk  = em [b * NT + t];
        const int src = si [b * NT + t];
        const int svv = sv [b * NT + t];
        const int ts  = tsi[b * NT + t];
        const int tsx = tsv[b * NT + t];
        const int tv  = tvi[b * NT + t];
        const int tvx = tvv[b * NT + t];
        const int src_c = min(max(src, 0), NS - 1);
        const int ts_c  = min(max(ts,  0), NS - 1);
        const int tv_c  = min(max(tv,  0), NV - 1);
        const bool mm = ((mk == 0) || (mk == 1)) && (svv > 0) && (tvx > 0);
        const bool sm = (mk == 2) && (svv > 0) && (tsx > 0);
        e_msrc[t] = src_c; e_mtgt[t] = tv_c; e_mval[t] = mm ? g_mg[b * NT + t] : 0.f;
        e_ssrc[t] = src_c; e_stgt[t] = ts_c; e_sval[t] = sm ? g_sg[b * NT + t] : 0.f;
    }
    if (tid == 0) {
        if (qv[b] > 0) {
            const int q = min(max(qi[b], 0), NS - 1);
            walk[q] = 1.0f;
        }
    }
    __syncthreads();

    float accs = 0.f;   // acc_s[d], d = tid

    for (int iter = 0; iter <= GRAPH_STEPS; iter++) {
        // acc_v += walk @ map_mem  (sparse, 12 edges)
        if (tid < NT) {
            const float c = walk[e_msrc[tid]] * e_mval[tid];
            if (c != 0.f) atomicAdd(&accv[e_mtgt[tid]], c);
        }
        // acc_s += walk @ symbol_emb  (gather only nonzero support, uniform branch)
        for (int s = 0; s < NS; s++) {
            const float w = walk[s];
            if (w != 0.f) accs = fmaf(w, symbol_emb[s * ND + tid], accs);
        }
        if (iter < GRAPH_STEPS) {
            __syncthreads();
            nwalk[tid] = 0.f; nwalk[tid + 256] = 0.f;
            __syncthreads();
            if (tid < NT) {
                const float c = walk[e_ssrc[tid]] * e_sval[tid];
                if (c != 0.f) atomicAdd(&nwalk[e_stgt[tid]], c);
            }
            __syncthreads();
            walk[tid] = nwalk[tid]; walk[tid + 256] = nwalk[tid + 256];
            __syncthreads();
        }
    }
    __syncthreads();  // accv atomics of final iter complete

    // acc_v @ value_emb — gather only nonzero accv rows (<=12)
    float vpart = 0.f;
    for (int v = 0; v < NV; v++) {
        const float a = accv[v];
        if (a != 0.f) vpart = fmaf(a, value_emb[v * ND + tid], vpart);
    }

    g_gs[b * 2 * ND + tid]      = accs;
    g_gs[b * 2 * ND + ND + tid] = vpart;
}

// ---------------------------------------------------------------------------
// Kernel 3: output MLPs.  4 rows per block (weight reuse), grid = NB/4.
// logits = mlp2(gs, Wo1, bo1, Wo2, bo2);  feedback = mlp2(gs, Wf1, bf1, Wf2, bf2)
// ---------------------------------------------------------------------------
constexpr int R3 = 4;

__global__ void out_kernel(const float* __restrict__ Wf1, const float* __restrict__ bf1,
                           const float* __restrict__ Wf2, const float* __restrict__ bf2,
                           const float* __restrict__ Wo1, const float* __restrict__ bo1,
                           const float* __restrict__ Wo2, const float* __restrict__ bo2,
                           float* __restrict__ out)
{
    __shared__ float gs[R3][2 * ND];   // 8 KB
    __shared__ float ho[R3][ND];       // 4 KB
    __shared__ float hf[R3][ND];       // 4 KB
    const int b0 = blockIdx.x * R3;
    const int j = threadIdx.x;

    #pragma unroll
    for (int r = 0; r < R3; r++) {
        gs[r][j]      = g_gs[(b0 + r) * 2 * ND + j];
        gs[r][j + ND] = g_gs[(b0 + r) * 2 * ND + ND + j];
    }
    __syncthreads();

    float so[R3], sf[R3];
    #pragma unroll
    for (int r = 0; r < R3; r++) { so[r] = 0.f; sf[r] = 0.f; }

    for (int i = 0; i < 2 * ND; i++) {
        const float wo = Wo1[i * ND + j];
        const float wf = Wf1[i * ND + j];
        #pragma unroll
        for (int r = 0; r < R3; r++) {
            const float g = gs[r][i];
            so[r] = fmaf(g, wo, so[r]);
            sf[r] = fmaf(g, wf, sf[r]);
        }
    }
    const float b1o = bo1[j], b1f = bf1[j];
    #pragma unroll
    for (int r = 0; r < R3; r++) {
        ho[r][j] = gelu_f(so[r] + b1o);
        hf[r][j] = gelu_f(sf[r] + b1f);
    }
    __syncthreads();

    float l0[R3], l1[R3], f0[R3];
    #pragma unroll
    for (int r = 0; r < R3; r++) { l0[r] = 0.f; l1[r] = 0.f; f0[r] = 0.f; }

    for (int i = 0; i < ND; i++) {
        const float w0 = Wo2[i * NV + j];
        const float w1 = Wo2[i * NV + j + ND];
        const float wf2v = Wf2[i * ND + j];
        #pragma unroll
        for (int r = 0; r < R3; r++) {
            l0[r] = fmaf(ho[r][i], w0,   l0[r]);
            l1[r] = fmaf(ho[r][i], w1,   l1[r]);
            f0[r] = fmaf(hf[r][i], wf2v, f0[r]);
        }
    }
    const float b2o0 = bo2[j], b2o1 = bo2[j + ND], b2f = bf2[j];
    #pragma unroll
    for (int r = 0; r < R3; r++) {
        const int b = b0 + r;
        out[b * NV + j]            = l0[r] + b2o0;
        out[b * NV + j + ND]       = l1[r] + b2o1;
        out[NB * NV + b * ND + j]  = f0[r] + b2f;   // feedback region after logits
    }
}

// ---------------------------------------------------------------------------
// Launch
// ---------------------------------------------------------------------------
extern "C" void kernel_launch(void* const* d_in, const int* in_sizes, int n_in,
                              void* d_out, int out_size)
{
    const int*   event_marker       = (const int*)  d_in[0];
    const int*   source_idx         = (const int*)  d_in[1];
    const int*   source_valid       = (const int*)  d_in[2];
    const int*   target_symbol_idx  = (const int*)  d_in[3];
    const int*   target_symbol_vld  = (const int*)  d_in[4];
    const int*   target_value_idx   = (const int*)  d_in[5];
    const int*   target_value_vld   = (const int*)  d_in[6];
    const int*   query_idx          = (const int*)  d_in[7];
    const int*   query_valid        = (const int*)  d_in[8];
    const float* evidence           = (const float*)d_in[9];
    const float* symbol_emb         = (const float*)d_in[10];
    const float* value_emb          = (const float*)d_in[11];
    const float* Wmg1 = (const float*)d_in[12];
    const float* bmg1 = (const float*)d_in[13];
    const float* Wmg2 = (const float*)d_in[14];
    const float* bmg2 = (const float*)d_in[15];
    const float* Wsg1 = (const float*)d_in[16];
    const float* bsg1 = (const float*)d_in[17];
    const float* Wsg2 = (const float*)d_in[18];
    const float* bsg2 = (const float*)d_in[19];
    const float* Wf1  = (const float*)d_in[20];
    const float* bf1  = (const float*)d_in[21];
    const float* Wf2  = (const float*)d_in[22];
    const float* bf2  = (const float*)d_in[23];
    const float* Wo1  = (const float*)d_in[24];
    const float* bo1  = (const float*)d_in[25];
    const float* Wo2  = (const float*)d_in[26];
    const float* bo2  = (const float*)d_in[27];

    float* out = (float*)d_out;

    gates_kernel<<<NB, ND>>>(evidence, Wmg1, bmg1, Wmg2, bmg2,
                             Wsg1, bsg1, Wsg2, bsg2);
    graph_kernel<<<NB, ND>>>(event_marker, source_idx, source_valid,
                             target_symbol_idx, target_symbol_vld,
                             target_value_idx, target_value_vld,
                             query_idx, query_valid, symbol_emb, value_emb);
    out_kernel<<<NB / R3, ND>>>(Wf1, bf1, Wf2, bf2, Wo1, bo1, Wo2, bo2, out);
}

// round 2
// speedup vs baseline: 2.3307x; 2.3307x over previous
#include <cuda_runtime.h>
#include <math.h>

constexpr int NB = 64;
constexpr int NT = 12;
constexpr int ND = 256;
constexpr int NS = 512;
constexpr int NV = 512;
constexpr int GRAPH_STEPS = 3;

// scratch: gate scalars  [g][b][t]
__device__ float g_gates[2 * NB * NT];

__device__ __forceinline__ float gelu_f(float x) {
    return 0.5f * x * (1.0f + erff(x * 0.70710678118654752440f));
}
__device__ __forceinline__ float sigmoid_f(float x) {
    return 1.0f / (1.0f + expf(-x));
}

// ---------------------------------------------------------------------------
// Kernel 1: gate MLPs.  grid = 128 blocks = (b, gate), 256 threads.
// Evidence transposed in smem: xT[d][r] (12 floats/row = 3 aligned float4)
// so the 12 broadcast operands per k-step are 3 x LDS.128.
// ---------------------------------------------------------------------------
__global__ void gates_kernel(const float* __restrict__ evidence,
                             const float* __restrict__ Wmg1, const float* __restrict__ bmg1,
                             const float* __restrict__ Wmg2, const float* __restrict__ bmg2,
                             const float* __restrict__ Wsg1, const float* __restrict__ bsg1,
                             const float* __restrict__ Wsg2, const float* __restrict__ bsg2)
{
    __shared__ float4 xTv[ND][3];        // xT[d][0..11], 12 KB, rows 16B-aligned
    __shared__ float red[NT][8];

    const int b = blockIdx.x >> 1;
    const int g = blockIdx.x & 1;        // 0 = map gate, 1 = step gate
    const int j = threadIdx.x;

    const float* __restrict__ W1 = g ? Wsg1 : Wmg1;
    const float* __restrict__ B1 = g ? bsg1 : bmg1;
    const float* __restrict__ W2 = g ? Wsg2 : Wmg2;
    const float* __restrict__ B2 = g ? bsg2 : bmg2;

    // transpose load: thread j owns column j of evidence -> row j of xT
    {
        float* xT = (float*)xTv;
        #pragma unroll
        for (int r = 0; r < NT; r++)
            xT[j * NT + r] = evidence[(b * NT + r) * ND + j];
    }
    __syncthreads();

    float acc[NT];
    #pragma unroll
    for (int r = 0; r < NT; r++) acc[r] = 0.f;

    #pragma unroll 4
    for (int d = 0; d < ND; d++) {
        const float w = W1[d * ND + j];
        const float4 a0 = xTv[d][0];
        const float4 a1 = xTv[d][1];
        const float4 a2 = xTv[d][2];
        acc[0]  = fmaf(a0.x, w, acc[0]);
        acc[1]  = fmaf(a0.y, w, acc[1]);
        acc[2]  = fmaf(a0.z, w, acc[2]);
        acc[3]  = fmaf(a0.w, w, acc[3]);
        acc[4]  = fmaf(a1.x, w, acc[4]);
        acc[5]  = fmaf(a1.y, w, acc[5]);
        acc[6]  = fmaf(a1.z, w, acc[6]);
        acc[7]  = fmaf(a1.w, w, acc[7]);
        acc[8]  = fmaf(a2.x, w, acc[8]);
        acc[9]  = fmaf(a2.y, w, acc[9]);
        acc[10] = fmaf(a2.z, w, acc[10]);
        acc[11] = fmaf(a2.w, w, acc[11]);
    }

    const float b1 = B1[j];
    const float w2 = W2[j];
    const int lane = j & 31, warp = j >> 5;

    #pragma unroll
    for (int r = 0; r < NT; r++) {
        float v = gelu_f(acc[r] + b1) * w2;
        #pragma unroll
        for (int off = 16; off > 0; off >>= 1)
            v += __shfl_xor_sync(0xffffffffu, v, off);
        if (lane == 0) red[r][warp] = v;
    }
    __syncthreads();

    if (j < NT) {
        float s = 0.f;
        #pragma unroll
        for (int w = 0; w < 8; w++) s += red[j][w];
        g_gates[(g * NB + b) * NT + j] = sigmoid_f(s + B2[0]);
    }
}

// ---------------------------------------------------------------------------
// Kernel 2: graph readout (sparse, candidate lists) + output MLPs.
// grid = 128 blocks = (b, branch), 256 threads.
// branch 0 = feedback (Wf), branch 1 = logits (Wo).
// ---------------------------------------------------------------------------
__global__ void graph_out_kernel(const int* __restrict__ em,  const int* __restrict__ si,
                                 const int* __restrict__ sv,  const int* __restrict__ tsi,
                                 const int* __restrict__ tsv, const int* __restrict__ tvi,
                                 const int* __restrict__ tvv, const int* __restrict__ qi,
                                 const int* __restrict__ qv,
                                 const float* __restrict__ symbol_emb,
                                 const float* __restrict__ value_emb,
                                 const float* __restrict__ Wf1, const float* __restrict__ bf1,
                                 const float* __restrict__ Wf2, const float* __restrict__ bf2,
                                 const float* __restrict__ Wo1, const float* __restrict__ bo1,
                                 const float* __restrict__ Wo2, const float* __restrict__ bo2,
                                 float* __restrict__ out)
{
    __shared__ float walk[NS], nwalk[NS], accv[NV];
    __shared__ float gs[2 * ND];
    __shared__ float h[ND];
    __shared__ int   e_msrc[NT], e_mtgt[NT], e_ssrc[NT], e_stgt[NT];
    __shared__ float e_mval[NT], e_sval[NT];
    __shared__ int   scand[NT + 1], vcand[NT];
    __shared__ int   n_scand, n_vcand;

    const int b   = blockIdx.x >> 1;
    const int br  = blockIdx.x & 1;
    const int tid = threadIdx.x;

    walk[tid] = 0.f;  walk[tid + 256] = 0.f;
    accv[tid] = 0.f;  accv[tid + 256] = 0.f;

    if (tid < NT) {
        const int t   = tid;
        const int mk  = em [b * NT + t];
        const int src = si [b * NT + t];
        const int svv = sv [b * NT + t];
        const int ts  = tsi[b * NT + t];
        const int tsx = tsv[b * NT + t];
        const int tv  = tvi[b * NT + t];
        const int tvx = tvv[b * NT + t];
        const int src_c = min(max(src, 0), NS - 1);
        const int ts_c  = min(max(ts,  0), NS - 1);
        const int tv_c  = min(max(tv,  0), NV - 1);
        const bool mm = ((mk == 0) || (mk == 1)) && (svv > 0) && (tvx > 0);
        const bool sm = (mk == 2) && (svv > 0) && (tsx > 0);
        e_msrc[t] = src_c; e_mtgt[t] = tv_c; e_mval[t] = mm ? g_gates[b * NT + t]            : 0.f;
        e_ssrc[t] = src_c; e_stgt[t] = ts_c; e_sval[t] = sm ? g_gates[(NB + b) * NT + t]     : 0.f;
    }
    __syncthreads();

    if (tid == 0) {
        const int q = min(max(qi[b], 0), NS - 1);
        if (qv[b] > 0) walk[q] = 1.0f;
        // dedup candidate lists: walk support subset {q} U step-targets,
        // accv support subset map-targets
        int n = 0;
        scand[n++] = q;
        for (int t = 0; t < NT; t++) {
            const int c = e_stgt[t];
            bool dup = false;
            for (int k = 0; k < n; k++) dup |= (scand[k] == c);
            if (!dup) scand[n++] = c;
        }
        n_scand = n;
        int m = 0;
        for (int t = 0; t < NT; t++) {
            const int c = e_mtgt[t];
            bool dup = false;
            for (int k = 0; k < m; k++) dup |= (vcand[k] == c);
            if (!dup) vcand[m++] = c;
        }
        n_vcand = m;
    }
    __syncthreads();

    float accs = 0.f;

    for (int iter = 0; iter <= GRAPH_STEPS; iter++) {
        // acc_v += walk @ map_mem (12 sparse edges)
        if (tid < NT) {
            const float c = walk[e_msrc[tid]] * e_mval[tid];
            if (c != 0.f) atomicAdd(&accv[e_mtgt[tid]], c);
        }
        // acc_s += walk @ symbol_emb over candidate support only
        const int nsc = n_scand;
        for (int c = 0; c < nsc; c++) {
            const int s = scand[c];
            accs = fmaf(walk[s], symbol_emb[s * ND + tid], accs);
        }
        if (iter < GRAPH_STEPS) {
            __syncthreads();
            nwalk[tid] = 0.f; nwalk[tid + 256] = 0.f;
            __syncthreads();
            if (tid < NT) {
                const float c = walk[e_ssrc[tid]] * e_sval[tid];
                if (c != 0.f) atomicAdd(&nwalk[e_stgt[tid]], c);
            }
            __syncthreads();
            walk[tid] = nwalk[tid]; walk[tid + 256] = nwalk[tid + 256];
            __syncthreads();
        }
    }
    __syncthreads();  // final accv atomics visible

    float vpart = 0.f;
    const int nvc = n_vcand;
    for (int c = 0; c < nvc; c++) {
        const int v = vcand[c];
        vpart = fmaf(accv[v], value_emb[v * ND + tid], vpart);
    }

    gs[tid]      = accs;
    gs[tid + ND] = vpart;
    __syncthreads();

    // ---- output MLP, this block's branch ----
    const float* __restrict__ W1 = br ? Wo1 : Wf1;
    const float* __restrict__ B1 = br ? bo1 : bf1;

    float a = 0.f;
    #pragma unroll 4
    for (int i = 0; i < 2 * ND; i += 4) {
        const float4 g4 = *(const float4*)&gs[i];
        a = fmaf(g4.x, W1[(i + 0) * ND + tid], a);
        a = fmaf(g4.y, W1[(i + 1) * ND + tid], a);
        a = fmaf(g4.z, W1[(i + 2) * ND + tid], a);
        a = fmaf(g4.w, W1[(i + 3) * ND + tid], a);
    }
    h[tid] = gelu_f(a + B1[tid]);
    __syncthreads();

    if (br) {
        // logits: [512] output cols, 2 per thread
        float a0 = 0.f, a1 = 0.f;
        #pragma unroll 4
        for (int i = 0; i < ND; i += 4) {
            const float4 h4 = *(const float4*)&h[i];
            a0 = fmaf(h4.x, Wo2[(i + 0) * NV + tid], a0);
            a1 = fmaf(h4.x, Wo2[(i + 0) * NV + tid + ND], a1);
            a0 = fmaf(h4.y, Wo2[(i + 1) * NV + tid], a0);
            a1 = fmaf(h4.y, Wo2[(i + 1) * NV + tid + ND], a1);
            a0 = fmaf(h4.z, Wo2[(i + 2) * NV + tid], a0);
            a1 = fmaf(h4.z, Wo2[(i + 2) * NV + tid + ND], a1);
            a0 = fmaf(h4.w, Wo2[(i + 3) * NV + tid], a0);
            a1 = fmaf(h4.w, Wo2[(i + 3) * NV + tid + ND], a1);
        }
        out[b * NV + tid]      = a0 + bo2[tid];
        out[b * NV + tid + ND] = a1 + bo2[tid + ND];
    } else {
        // feedback: [256] output cols
        float a0 = 0.f;
        #pragma unroll 4
        for (int i = 0; i < ND; i += 4) {
            const float4 h4 = *(const float4*)&h[i];
            a0 = fmaf(h4.x, Wf2[(i + 0) * ND + tid], a0);
            a0 = fmaf(h4.y, Wf2[(i + 1) * ND + tid], a0);
            a0 = fmaf(h4.z, Wf2[(i + 2) * ND + tid], a0);
            a0 = fmaf(h4.w, Wf2[(i + 3) * ND + tid], a0);
        }
        out[NB * NV + b * ND + tid] = a0 + bf2[tid];
    }
}

// ---------------------------------------------------------------------------
extern "C" void kernel_launch(void* const* d_in, const int* in_sizes, int n_in,
                              void* d_out, int out_size)
{
    const int*   event_marker       = (const int*)  d_in[0];
    const int*   source_idx         = (const int*)  d_in[1];
    const int*   source_valid       = (const int*)  d_in[2];
    const int*   target_symbol_idx  = (const int*)  d_in[3];
    const int*   target_symbol_vld  = (const int*)  d_in[4];
    const int*   target_value_idx   = (const int*)  d_in[5];
    const int*   target_value_vld   = (const int*)  d_in[6];
    const int*   query_idx          = (const int*)  d_in[7];
    const int*   query_valid        = (const int*)  d_in[8];
    const float* evidence           = (const float*)d_in[9];
    const float* symbol_emb         = (const float*)d_in[10];
    const float* value_emb          = (const float*)d_in[11];
    const float* Wmg1 = (const float*)d_in[12];
    const float* bmg1 = (const float*)d_in[13];
    const float* Wmg2 = (const float*)d_in[14];
    const float* bmg2 = (const float*)d_in[15];
    const float* Wsg1 = (const float*)d_in[16];
    const float* bsg1 = (const float*)d_in[17];
    const float* Wsg2 = (const float*)d_in[18];
    const float* bsg2 = (const float*)d_in[19];
    const float* Wf1  = (const float*)d_in[20];
    const float* bf1  = (const float*)d_in[21];
    const float* Wf2  = (const float*)d_in[22];
    const float* bf2  = (const float*)d_in[23];
    const float* Wo1  = (const float*)d_in[24];
    const float* bo1  = (const float*)d_in[25];
    const float* Wo2  = (const float*)d_in[26];
    const float* bo2  = (const float*)d_in[27];

    float* out = (float*)d_out;

    gates_kernel<<<2 * NB, ND>>>(evidence, Wmg1, bmg1, Wmg2, bmg2,
                                 Wsg1, bsg1, Wsg2, bsg2);
    graph_out_kernel<<<2 * NB, ND>>>(event_marker, source_idx, source_valid,
                                     target_symbol_idx, target_symbol_vld,
                                     target_value_idx, target_value_vld,
                                     query_idx, query_valid,
                                     symbol_emb, value_emb,
                                     Wf1, bf1, Wf2, bf2,
                                     Wo1, bo1, Wo2, bo2, out);
}

// round 3
// speedup vs baseline: 3.4038x; 1.4604x over previous
#include <cuda_runtime.h>
#include <math.h>

constexpr int NB = 64;
constexpr int NT = 12;
constexpr int ND = 256;
constexpr int NS = 512;
constexpr int NV = 512;
constexpr int GRAPH_STEPS = 3;

// scratch: gate scalars  [g][b][t]
__device__ float g_gates[2 * NB * NT];

__device__ __forceinline__ float gelu_f(float x) {
    return 0.5f * x * (1.0f + erff(x * 0.70710678118654752440f));
}
__device__ __forceinline__ float sigmoid_f(float x) {
    return 1.0f / (1.0f + expf(-x));
}

// ---------------------------------------------------------------------------
// Kernel 1: gate MLPs.  grid = 128 = (b, gate), 512 threads (K-split by 2).
// ---------------------------------------------------------------------------
__global__ void gates_kernel(const float* __restrict__ evidence,
                             const float* __restrict__ Wmg1, const float* __restrict__ bmg1,
                             const float* __restrict__ Wmg2, const float* __restrict__ bmg2,
                             const float* __restrict__ Wsg1, const float* __restrict__ bsg1,
                             const float* __restrict__ Wsg2, const float* __restrict__ bsg2)
{
    __shared__ float4 xTv[ND][3];        // xT[d][0..11]
    __shared__ float padd[NT][ND];       // partial from K-half 1
    __shared__ float red[NT][8];

    const int b = blockIdx.x >> 1;
    const int g = blockIdx.x & 1;
    const int tid  = threadIdx.x;
    const int j    = tid & (ND - 1);
    const int half = tid >> 8;           // 0 or 1

    const float* __restrict__ W1 = g ? Wsg1 : Wmg1;
    const float* __restrict__ B1 = g ? bsg1 : bmg1;
    const float* __restrict__ W2 = g ? Wsg2 : Wmg2;
    const float* __restrict__ B2 = g ? bsg2 : bmg2;

    {
        float* xT = (float*)xTv;
        #pragma unroll
        for (int r = half * 6; r < half * 6 + 6; r++)
            xT[j * NT + r] = evidence[(b * NT + r) * ND + j];
    }
    __syncthreads();

    float acc[NT];
    #pragma unroll
    for (int r = 0; r < NT; r++) acc[r] = 0.f;

    const int d0 = half * (ND / 2);
    #pragma unroll 4
    for (int d = d0; d < d0 + ND / 2; d++) {
        const float w = W1[d * ND + j];
        const float4 a0 = xTv[d][0];
        const float4 a1 = xTv[d][1];
        const float4 a2 = xTv[d][2];
        acc[0]  = fmaf(a0.x, w, acc[0]);
        acc[1]  = fmaf(a0.y, w, acc[1]);
        acc[2]  = fmaf(a0.z, w, acc[2]);
        acc[3]  = fmaf(a0.w, w, acc[3]);
        acc[4]  = fmaf(a1.x, w, acc[4]);
        acc[5]  = fmaf(a1.y, w, acc[5]);
        acc[6]  = fmaf(a1.z, w, acc[6]);
        acc[7]  = fmaf(a1.w, w, acc[7]);
        acc[8]  = fmaf(a2.x, w, acc[8]);
        acc[9]  = fmaf(a2.y, w, acc[9]);
        acc[10] = fmaf(a2.z, w, acc[10]);
        acc[11] = fmaf(a2.w, w, acc[11]);
    }

    if (half == 1) {
        #pragma unroll
        for (int r = 0; r < NT; r++) padd[r][j] = acc[r];
    }
    __syncthreads();

    if (half == 0) {
        const float b1 = B1[j];
        const float w2 = W2[j];
        const int lane = j & 31, warp = j >> 5;
        #pragma unroll
        for (int r = 0; r < NT; r++) {
            float v = gelu_f(acc[r] + padd[r][j] + b1) * w2;
            #pragma unroll
            for (int off = 16; off > 0; off >>= 1)
                v += __shfl_xor_sync(0xffffffffu, v, off);
            if (lane == 0) red[r][warp] = v;
        }
    }
    __syncthreads();

    if (tid < NT) {
        float s = 0.f;
        #pragma unroll
        for (int w = 0; w < 8; w++) s += red[tid][w];
        g_gates[(g * NB + b) * NT + tid] = sigmoid_f(s + B2[0]);
    }
}

// ---------------------------------------------------------------------------
// Kernel 2: sparse graph readout + output MLPs.
// grid = 128 = (b, branch), 1024 threads.  All dot products K-split across
// thread groups with smem partial reduction -> 4x the loads in flight.
// ---------------------------------------------------------------------------
__global__ void __launch_bounds__(1024, 1)
graph_out_kernel(const int* __restrict__ em,  const int* __restrict__ si,
                 const int* __restrict__ sv,  const int* __restrict__ tsi,
                 const int* __restrict__ tsv, const int* __restrict__ tvi,
                 const int* __restrict__ tvv, const int* __restrict__ qi,
                 const int* __restrict__ qv,
                 const float* __restrict__ symbol_emb,
                 const float* __restrict__ value_emb,
                 const float* __restrict__ Wf1, const float* __restrict__ bf1,
                 const float* __restrict__ Wf2, const float* __restrict__ bf2,
                 const float* __restrict__ Wo1, const float* __restrict__ bo1,
                 const float* __restrict__ Wo2, const float* __restrict__ bo2,
                 float* __restrict__ out)
{
    __shared__ float walk[NS], nwalk[NS], accv[NV];
    __shared__ float gs[2 * ND];
    __shared__ float h[ND];
    __shared__ float part[1024];         // reduction scratch, reused per phase
    __shared__ float part2[1024];
    __shared__ int   e_msrc[NT], e_mtgt[NT], e_ssrc[NT], e_stgt[NT];
    __shared__ float e_mval[NT], e_sval[NT];
    __shared__ int   scand[NT + 1], vcand[NT];
    __shared__ int   n_scand, n_vcand;

    const int b   = blockIdx.x >> 1;
    const int br  = blockIdx.x & 1;
    const int tid = threadIdx.x;
    const int d   = tid & (ND - 1);      // 0..255
    const int grp = tid >> 8;            // 0..3

    if (tid < NS) { walk[tid] = 0.f; accv[tid] = 0.f; }

    if (tid < NT) {
        const int t   = tid;
        const int mk  = em [b * NT + t];
        const int src = si [b * NT + t];
        const int svv = sv [b * NT + t];
        const int ts  = tsi[b * NT + t];
        const int tsx = tsv[b * NT + t];
        const int tv  = tvi[b * NT + t];
        const int tvx = tvv[b * NT + t];
        const int src_c = min(max(src, 0), NS - 1);
        const int ts_c  = min(max(ts,  0), NS - 1);
        const int tv_c  = min(max(tv,  0), NV - 1);
        const bool mm = ((mk == 0) || (mk == 1)) && (svv > 0) && (tvx > 0);
        const bool sm = (mk == 2) && (svv > 0) && (tsx > 0);
        e_msrc[t] = src_c; e_mtgt[t] = tv_c; e_mval[t] = mm ? g_gates[b * NT + t]        : 0.f;
        e_ssrc[t] = src_c; e_stgt[t] = ts_c; e_sval[t] = sm ? g_gates[(NB + b) * NT + t] : 0.f;
    }
    __syncthreads();

    if (tid == 0) {
        const int q = min(max(qi[b], 0), NS - 1);
        if (qv[b] > 0) walk[q] = 1.0f;
        int n = 0;
        scand[n++] = q;
        for (int t = 0; t < NT; t++) {
            const int c = e_stgt[t];
            bool dup = false;
            for (int k = 0; k < n; k++) dup |= (scand[k] == c);
            if (!dup) scand[n++] = c;
        }
        n_scand = n;
        int m = 0;
        for (int t = 0; t < NT; t++) {
            const int c = e_mtgt[t];
            bool dup = false;
            for (int k = 0; k < m; k++) dup |= (vcand[k] == c);
            if (!dup) vcand[m++] = c;
        }
        n_vcand = m;
    }
    __syncthreads();

    float accs = 0.f;   // this (grp,d)'s partial of acc_s[d]

    for (int iter = 0; iter <= GRAPH_STEPS; iter++) {
        if (tid < NT) {
            const float c = walk[e_msrc[tid]] * e_mval[tid];
            if (c != 0.f) atomicAdd(&accv[e_mtgt[tid]], c);
        }
        const int nsc = n_scand;
        for (int c = grp; c < nsc; c += 4) {
            const int s = scand[c];
            accs = fmaf(walk[s], symbol_emb[s * ND + d], accs);
        }
        if (iter < GRAPH_STEPS) {
            __syncthreads();
            if (tid < NS) nwalk[tid] = 0.f;
            __syncthreads();
            if (tid < NT) {
                const float c = walk[e_ssrc[tid]] * e_sval[tid];
                if (c != 0.f) atomicAdd(&nwalk[e_stgt[tid]], c);
            }
            __syncthreads();
            if (tid < NS) walk[tid] = nwalk[tid];
            __syncthreads();
        }
    }
    __syncthreads();  // final accv atomics visible

    float vpart = 0.f;
    const int nvc = n_vcand;
    for (int c = grp; c < nvc; c += 4) {
        const int v = vcand[c];
        vpart = fmaf(accv[v], value_emb[v * ND + d], vpart);
    }

    part[tid]  = accs;
    part2[tid] = vpart;
    __syncthreads();
    if (tid < ND) {
        gs[tid]      = part [tid] + part [tid + 256] + part [tid + 512] + part [tid + 768];
        gs[tid + ND] = part2[tid] + part2[tid + 256] + part2[tid + 512] + part2[tid + 768];
    }
    __syncthreads();

    // ---- layer 1: h = gelu(gs @ W1 + b1), K=512 split across 4 groups ----
    const float* __restrict__ W1 = br ? Wo1 : Wf1;
    const float* __restrict__ B1 = br ? bo1 : bf1;
    {
        float a = 0.f;
        const int i0 = grp * 128;
        #pragma unroll 4
        for (int i = i0; i < i0 + 128; i += 4) {
            const float4 g4 = *(const float4*)&gs[i];
            a = fmaf(g4.x, W1[(i + 0) * ND + d], a);
            a = fmaf(g4.y, W1[(i + 1) * ND + d], a);
            a = fmaf(g4.z, W1[(i + 2) * ND + d], a);
            a = fmaf(g4.w, W1[(i + 3) * ND + d], a);
        }
        part[tid] = a;
    }
    __syncthreads();
    if (tid < ND)
        h[tid] = gelu_f(part[tid] + part[tid + 256] + part[tid + 512] + part[tid + 768]
                        + B1[tid]);
    __syncthreads();

    // ---- layer 2 ----
    if (br) {
        // logits: 512 cols, K=256 split across 2 halves
        const int col = tid & (NV - 1);
        const int kh  = tid >> 9;
        float a = 0.f;
        const int i0 = kh * 128;
        #pragma unroll 4
        for (int i = i0; i < i0 + 128; i += 4) {
            const float4 h4 = *(const float4*)&h[i];
            a = fmaf(h4.x, Wo2[(i + 0) * NV + col], a);
            a = fmaf(h4.y, Wo2[(i + 1) * NV + col], a);
            a = fmaf(h4.z, Wo2[(i + 2) * NV + col], a);
            a = fmaf(h4.w, Wo2[(i + 3) * NV + col], a);
        }
        part[tid] = a;
        __syncthreads();
        if (tid < NV)
            out[b * NV + tid] = part[tid] + part[tid + 512] + bo2[tid];
    } else {
        // feedback: 256 cols, K=256 split across 4 groups
        float a = 0.f;
        const int i0 = grp * 64;
        #pragma unroll 4
        for (int i = i0; i < i0 + 64; i += 4) {
            const float4 h4 = *(const float4*)&h[i];
            a = fmaf(h4.x, Wf2[(i + 0) * ND + d], a);
            a = fmaf(h4.y, Wf2[(i + 1) * ND + d], a);
            a = fmaf(h4.z, Wf2[(i + 2) * ND + d], a);
            a = fmaf(h4.w, Wf2[(i + 3) * ND + d], a);
        }
        part[tid] = a;
        __syncthreads();
        if (tid < ND)
            out[NB * NV + b * ND + tid] =
                part[tid] + part[tid + 256] + part[tid + 512] + part[tid + 768] + bf2[tid];
    }
}

// ---------------------------------------------------------------------------
extern "C" void kernel_launch(void* const* d_in, const int* in_sizes, int n_in,
                              void* d_out, int out_size)
{
    const int*   event_marker       = (const int*)  d_in[0];
    const int*   source_idx         = (const int*)  d_in[1];
    const int*   source_valid       = (const int*)  d_in[2];
    const int*   target_symbol_idx  = (const int*)  d_in[3];
    const int*   target_symbol_vld  = (const int*)  d_in[4];
    const int*   target_value_idx   = (const int*)  d_in[5];
    const int*   target_value_vld   = (const int*)  d_in[6];
    const int*   query_idx          = (const int*)  d_in[7];
    const int*   query_valid        = (const int*)  d_in[8];
    const float* evidence           = (const float*)d_in[9];
    const float* symbol_emb         = (const float*)d_in[10];
    const float* value_emb          = (const float*)d_in[11];
    const float* Wmg1 = (const float*)d_in[12];
    const float* bmg1 = (const float*)d_in[13];
    const float* Wmg2 = (const float*)d_in[14];
    const float* bmg2 = (const float*)d_in[15];
    const float* Wsg1 = (const float*)d_in[16];
    const float* bsg1 = (const float*)d_in[17];
    const float* Wsg2 = (const float*)d_in[18];
    const float* bsg2 = (const float*)d_in[19];
    const float* Wf1  = (const float*)d_in[20];
    const float* bf1  = (const float*)d_in[21];
    const float* Wf2  = (const float*)d_in[22];
    const float* bf2  = (const float*)d_in[23];
    const float* Wo1  = (const float*)d_in[24];
    const float* bo1  = (const float*)d_in[25];
    const float* Wo2  = (const float*)d_in[26];
    const float* bo2  = (const float*)d_in[27];

    float* out = (float*)d_out;

    gates_kernel<<<2 * NB, 512>>>(evidence, Wmg1, bmg1, Wmg2, bmg2,
                                  Wsg1, bsg1, Wsg2, bsg2);
    graph_out_kernel<<<2 * NB, 1024>>>(event_marker, source_idx, source_valid,
                                       target_symbol_idx, target_symbol_vld,
                                       target_value_idx, target_value_vld,
                                       query_idx, query_valid,
                                       symbol_emb, value_emb,
                                       Wf1, bf1, Wf2, bf2,
                                       Wo1, bo1, Wo2, bo2, out);
}

// round 4
// speedup vs baseline: 3.9386x; 1.1571x over previous
#include <cuda_runtime.h>
#include <math.h>

constexpr int NB = 64;
constexpr int NT = 12;
constexpr int ND = 256;
constexpr int NS = 512;
constexpr int NV = 512;
constexpr int GRAPH_STEPS = 3;

// scratch: gate scalars  [g][b][t]
__device__ float g_gates[2 * NB * NT];

__device__ __forceinline__ float gelu_f(float x) {
    return 0.5f * x * (1.0f + erff(x * 0.70710678118654752440f));
}
__device__ __forceinline__ float sigmoid_f(float x) {
    return 1.0f / (1.0f + expf(-x));
}

// ---- packed f32x2 helpers (FFMA2 path, sm_103a) ----
__device__ __forceinline__ unsigned long long pk2(float lo, float hi) {
    unsigned long long r;
    asm("mov.b64 %0, {%1, %2};" : "=l"(r) : "f"(lo), "f"(hi));
    return r;
}
__device__ __forceinline__ unsigned long long fma2(unsigned long long a,
                                                   unsigned long long b,
                                                   unsigned long long c) {
    unsigned long long d;
    asm("fma.rn.f32x2 %0, %1, %2, %3;" : "=l"(d) : "l"(a), "l"(b), "l"(c));
    return d;
}
__device__ __forceinline__ float2 upk(unsigned long long v) {
    float2 f;
    asm("mov.b64 {%0, %1}, %2;" : "=f"(f.x), "=f"(f.y) : "l"(v));
    return f;
}

// ---------------------------------------------------------------------------
// Kernel 1: gate MLPs.  grid = 128 = (b, gate), 1024 threads.
// K-split 4; evidence transposed in smem as row-pairs (u64) so the f32x2
// FMA operands need zero packing; weight broadcast packed once per k.
// ---------------------------------------------------------------------------
__global__ void __launch_bounds__(1024, 1)
gates_kernel(const float* __restrict__ evidence,
             const float* __restrict__ Wmg1, const float* __restrict__ bmg1,
             const float* __restrict__ Wmg2, const float* __restrict__ bmg2,
             const float* __restrict__ Wsg1, const float* __restrict__ bsg1,
             const float* __restrict__ Wsg2, const float* __restrict__ bsg2)
{
    // union: xT (12KB) during compute, partials (36KB) after
    __shared__ __align__(16) char ubuf[3 * NT * ND * 4];
    __shared__ float red[NT][8];

    const int b   = blockIdx.x >> 1;
    const int g   = blockIdx.x & 1;
    const int tid = threadIdx.x;
    const int j   = tid & (ND - 1);      // hidden col
    const int kg  = tid >> 8;            // 0..3 K-group

    const float* __restrict__ W1 = g ? Wsg1 : Wmg1;
    const float* __restrict__ B1 = g ? bsg1 : bmg1;
    const float* __restrict__ W2 = g ? Wsg2 : Wmg2;
    const float* __restrict__ B2 = g ? bsg2 : bmg2;

    // transpose-load evidence: xT[d][r], rows of 12 floats (48B, 16B aligned)
    {
        float* xT = (float*)ubuf;
        #pragma unroll
        for (int r = kg * 3; r < kg * 3 + 3; r++)
            xT[j * NT + r] = evidence[(b * NT + r) * ND + j];
    }
    __syncthreads();

    unsigned long long acc[6];
    #pragma unroll
    for (int p = 0; p < 6; p++) acc[p] = 0ull;

    const ulonglong2* __restrict__ xTv = (const ulonglong2*)ubuf;  // [d][3]
    const int k0 = kg * 64;
    #pragma unroll 4
    for (int k = k0; k < k0 + 64; k++) {
        const float w = W1[k * ND + j];
        const unsigned long long wp = pk2(w, w);
        const ulonglong2 p0 = xTv[k * 3 + 0];
        const ulonglong2 p1 = xTv[k * 3 + 1];
        const ulonglong2 p2 = xTv[k * 3 + 2];
        acc[0] = fma2(p0.x, wp, acc[0]);
        acc[1] = fma2(p0.y, wp, acc[1]);
        acc[2] = fma2(p1.x, wp, acc[2]);
        acc[3] = fma2(p1.y, wp, acc[3]);
        acc[4] = fma2(p2.x, wp, acc[4]);
        acc[5] = fma2(p2.y, wp, acc[5]);
    }
    __syncthreads();   // everyone done reading xT; ubuf becomes partials

    float (*part)[NT][ND] = (float (*)[NT][ND])ubuf;   // [3][12][256]
    if (kg > 0) {
        #pragma unroll
        for (int p = 0; p < 6; p++) {
            const float2 f = upk(acc[p]);
            part[kg - 1][2 * p][j]     = f.x;
            part[kg - 1][2 * p + 1][j] = f.y;
        }
    }
    __syncthreads();

    if (kg == 0) {
        const float b1 = B1[j];
        const float w2 = W2[j];
        const int lane = j & 31, warp = j >> 5;
        #pragma unroll
        for (int p = 0; p < 6; p++) {
            const float2 f = upk(acc[p]);
            #pragma unroll
            for (int hh = 0; hh < 2; hh++) {
                const int r = 2 * p + hh;
                float v = (hh ? f.y : f.x)
                        + part[0][r][j] + part[1][r][j] + part[2][r][j] + b1;
                v = gelu_f(v) * w2;
                #pragma unroll
                for (int off = 16; off > 0; off >>= 1)
                    v += __shfl_xor_sync(0xffffffffu, v, off);
                if (lane == 0) red[r][warp] = v;
            }
        }
    }
    __syncthreads();

    if (tid < NT) {
        float s = 0.f;
        #pragma unroll
        for (int w = 0; w < 8; w++) s += red[tid][w];
        g_gates[(g * NB + b) * NT + tid] = sigmoid_f(s + B2[0]);
    }
}

// ---------------------------------------------------------------------------
// Kernel 2: sparse graph readout + output MLPs.
// grid = 128 = (b, branch), 1024 threads.
// Walk evolution runs entirely in warp 0 (support <= 13), producing summed
// weights wsum/vw; single gather afterwards.  MLP layers use 128-bit weight
// loads (4-col quads) + FFMA2 + deep K-split.
// ---------------------------------------------------------------------------
__global__ void __launch_bounds__(1024, 1)
graph_out_kernel(const int* __restrict__ em,  const int* __restrict__ si,
                 const int* __restrict__ sv,  const int* __restrict__ tsi,
                 const int* __restrict__ tsv, const int* __restrict__ tvi,
                 const int* __restrict__ tvv, const int* __restrict__ qi,
                 const int* __restrict__ qv,
                 const float* __restrict__ symbol_emb,
                 const float* __restrict__ value_emb,
                 const float* __restrict__ Wf1, const float* __restrict__ bf1,
                 const float* __restrict__ Wf2, const float* __restrict__ bf2,
                 const float* __restrict__ Wo1, const float* __restrict__ bo1,
                 const float* __restrict__ Wo2, const float* __restrict__ bo2,
                 float* __restrict__ out)
{
    __shared__ float walk[NS], nwalk[NS];
    __shared__ float wsum[NS], vw[NV];
    __shared__ float gs[2 * ND];
    __shared__ float h[ND];
    __shared__ __align__(16) float part[4 * 1024];   // 16KB reduction scratch
    __shared__ float part2[1024];
    __shared__ int   e_msrc[NT], e_mtgt[NT], e_ssrc[NT], e_stgt[NT];
    __shared__ float e_mval[NT], e_sval[NT];
    __shared__ int   scand[NT + 1], vcand[NT];
    __shared__ int   n_scand, n_vcand;

    const int b   = blockIdx.x >> 1;
    const int br  = blockIdx.x & 1;
    const int tid = threadIdx.x;
    const int d   = tid & (ND - 1);
    const int grp = tid >> 8;

    if (tid < NS) { walk[tid] = 0.f; wsum[tid] = 0.f; vw[tid] = 0.f; }

    if (tid < NT) {
        const int t   = tid;
        const int mk  = em [b * NT + t];
        const int src = si [b * NT + t];
        const int svv = sv [b * NT + t];
        const int ts  = tsi[b * NT + t];
        const int tsx = tsv[b * NT + t];
        const int tv  = tvi[b * NT + t];
        const int tvx = tvv[b * NT + t];
        const int src_c = min(max(src, 0), NS - 1);
        const int ts_c  = min(max(ts,  0), NS - 1);
        const int tv_c  = min(max(tv,  0), NV - 1);
        const bool mm = ((mk == 0) || (mk == 1)) && (svv > 0) && (tvx > 0);
        const bool sm = (mk == 2) && (svv > 0) && (tsx > 0);
        e_msrc[t] = src_c; e_mtgt[t] = tv_c; e_mval[t] = mm ? g_gates[b * NT + t]        : 0.f;
        e_ssrc[t] = src_c; e_stgt[t] = ts_c; e_sval[t] = sm ? g_gates[(NB + b) * NT + t] : 0.f;
    }
    __syncthreads();

    if (tid == 0) {
        const int q = min(max(qi[b], 0), NS - 1);
        if (qv[b] > 0) walk[q] = 1.0f;
        int n = 0;
        scand[n++] = q;
        for (int t = 0; t < NT; t++) {
            const int c = e_stgt[t];
            bool dup = false;
            for (int k = 0; k < n; k++) dup |= (scand[k] == c);
            if (!dup) scand[n++] = c;
        }
        n_scand = n;
        int m = 0;
        for (int t = 0; t < NT; t++) {
            const int c = e_mtgt[t];
            bool dup = false;
            for (int k = 0; k < m; k++) dup |= (vcand[k] == c);
            if (!dup) vcand[m++] = c;
        }
        n_vcand = m;
    }
    __syncthreads();

    // ---- walk evolution, warp 0 only (support <= 13) ----
    if (tid < 32) {
        const int nsc = n_scand;
        for (int iter = 0; iter <= GRAPH_STEPS; iter++) {
            if (tid < nsc) wsum[scand[tid]] += walk[scand[tid]];
            if (tid < NT) {
                const float c = walk[e_msrc[tid]] * e_mval[tid];
                if (c != 0.f) atomicAdd(&vw[e_mtgt[tid]], c);
            }
            __syncwarp();
            if (iter < GRAPH_STEPS) {
                if (tid < nsc) nwalk[scand[tid]] = 0.f;
                __syncwarp();
                if (tid < NT) {
                    const float c = walk[e_ssrc[tid]] * e_sval[tid];
                    if (c != 0.f) atomicAdd(&nwalk[e_stgt[tid]], c);
                }
                __syncwarp();
                if (tid < nsc) walk[scand[tid]] = nwalk[scand[tid]];
                __syncwarp();
            }
        }
    }
    __syncthreads();

    // ---- single sparse gather: gs = [acc_s, acc_v @ value_emb] ----
    {
        float accs = 0.f, vpart = 0.f;
        const int nsc = n_scand, nvc = n_vcand;
        for (int c = grp; c < nsc; c += 4) {
            const int s = scand[c];
            accs = fmaf(wsum[s], symbol_emb[s * ND + d], accs);
        }
        for (int c = grp; c < nvc; c += 4) {
            const int v = vcand[c];
            vpart = fmaf(vw[v], value_emb[v * ND + d], vpart);
        }
        part[tid]  = accs;
        part2[tid] = vpart;
    }
    __syncthreads();
    if (tid < ND) {
        gs[tid]      = part [tid] + part [tid + 256] + part [tid + 512] + part [tid + 768];
        gs[tid + ND] = part2[tid] + part2[tid + 256] + part2[tid + 512] + part2[tid + 768];
    }
    __syncthreads();

    // ---- layer 1: h = gelu(gs @ W1 + b1).  quads of 4 cols, K-split 16 ----
    const float* __restrict__ W1 = br ? Wo1 : Wf1;
    const float* __restrict__ B1 = br ? bo1 : bf1;
    {
        const int q  = tid & 63;         // col quad: cols 4q..4q+3
        const int kg = tid >> 6;         // 0..15
        unsigned long long a0 = 0ull, a1 = 0ull;
        const int k0 = kg * 32;
        #pragma unroll 8
        for (int k = k0; k < k0 + 32; k++) {
            const ulonglong2 wv = *(const ulonglong2*)&W1[k * ND + 4 * q];
            const unsigned long long g2 = pk2(gs[k], gs[k]);
            a0 = fma2(g2, wv.x, a0);
            a1 = fma2(g2, wv.y, a1);
        }
        const float2 f0 = upk(a0), f1 = upk(a1);
        float4* p4 = (float4*)part;
        p4[tid] = make_float4(f0.x, f0.y, f1.x, f1.y);
    }
    __syncthreads();
    if (tid < ND) {
        const int q = tid >> 2, cp = tid & 3;
        float s = 0.f;
        #pragma unroll
        for (int kg = 0; kg < 16; kg++)
            s += part[(kg * 64 + q) * 4 + cp];
        h[tid] = gelu_f(s + B1[tid]);
    }
    __syncthreads();

    // ---- layer 2 ----
    if (br) {
        // logits: 512 cols -> 128 quads, K-split 8
        const int q  = tid & 127;
        const int kg = tid >> 7;         // 0..7
        unsigned long long a0 = 0ull, a1 = 0ull;
        const int k0 = kg * 32;
        #pragma unroll 8
        for (int k = k0; k < k0 + 32; k++) {
            const ulonglong2 wv = *(const ulonglong2*)&Wo2[k * NV + 4 * q];
            const unsigned long long h2 = pk2(h[k], h[k]);
            a0 = fma2(h2, wv.x, a0);
            a1 = fma2(h2, wv.y, a1);
        }
        const float2 f0 = upk(a0), f1 = upk(a1);
        float4* p4 = (float4*)part;
        p4[tid] = make_float4(f0.x, f0.y, f1.x, f1.y);
        __syncthreads();
        if (tid < NV) {
            const int q2 = tid >> 2, cp = tid & 3;
            float s = 0.f;
            #pragma unroll
            for (int kg2 = 0; kg2 < 8; kg2++)
                s += part[(kg2 * 128 + q2) * 4 + cp];
            out[b * NV + tid] = s + bo2[tid];
        }
    } else {
        // feedback: 256 cols -> 64 quads, K-split 16
        const int q  = tid & 63;
        const int kg = tid >> 6;         // 0..15
        unsigned long long a0 = 0ull, a1 = 0ull;
        const int k0 = kg * 16;
        #pragma unroll 8
        for (int k = k0; k < k0 + 16; k++) {
            const ulonglong2 wv = *(const ulonglong2*)&Wf2[k * ND + 4 * q];
            const unsigned long long h2 = pk2(h[k], h[k]);
            a0 = fma2(h2, wv.x, a0);
            a1 = fma2(h2, wv.y, a1);
        }
        const float2 f0 = upk(a0), f1 = upk(a1);
        float4* p4 = (float4*)part;
        p4[tid] = make_float4(f0.x, f0.y, f1.x, f1.y);
        __syncthreads();
        if (tid < ND) {
            const int q2 = tid >> 2, cp = tid & 3;
            float s = 0.f;
            #pragma unroll
            for (int kg2 = 0; kg2 < 16; kg2++)
                s += part[(kg2 * 64 + q2) * 4 + cp];
            out[NB * NV + b * ND + tid] = s + bf2[tid];
        }
    }
}

// ---------------------------------------------------------------------------
extern "C" void kernel_launch(void* const* d_in, const int* in_sizes, int n_in,
                              void* d_out, int out_size)
{
    const int*   event_marker       = (const int*)  d_in[0];
    const int*   source_idx         = (const int*)  d_in[1];
    const int*   source_valid       = (const int*)  d_in[2];
    const int*   target_symbol_idx  = (const int*)  d_in[3];
    const int*   target_symbol_vld  = (const int*)  d_in[4];
    const int*   target_value_idx   = (const int*)  d_in[5];
    const int*   target_value_vld   = (const int*)  d_in[6];
    const int*   query_idx          = (const int*)  d_in[7];
    const int*   query_valid        = (const int*)  d_in[8];
    const float* evidence           = (const float*)d_in[9];
    const float* symbol_emb         = (const float*)d_in[10];
    const float* value_emb          = (const float*)d_in[11];
    const float* Wmg1 = (const float*)d_in[12];
    const float* bmg1 = (const float*)d_in[13];
    const float* Wmg2 = (const float*)d_in[14];
    const float* bmg2 = (const float*)d_in[15];
    const float* Wsg1 = (const float*)d_in[16];
    const float* bsg1 = (const float*)d_in[17];
    const float* Wsg2 = (const float*)d_in[18];
    const float* bsg2 = (const float*)d_in[19];
    const float* Wf1  = (const float*)d_in[20];
    const float* bf1  = (const float*)d_in[21];
    const float* Wf2  = (const float*)d_in[22];
    const float* bf2  = (const float*)d_in[23];
    const float* Wo1  = (const float*)d_in[24];
    const float* bo1  = (const float*)d_in[25];
    const float* Wo2  = (const float*)d_in[26];
    const float* bo2  = (const float*)d_in[27];

    float* out = (float*)d_out;

    gates_kernel<<<2 * NB, 1024>>>(evidence, Wmg1, bmg1, Wmg2, bmg2,
                                   Wsg1, bsg1, Wsg2, bsg2);
    graph_out_kernel<<<2 * NB, 1024>>>(event_marker, source_idx, source_valid,
                                       target_symbol_idx, target_symbol_vld,
                                       target_value_idx, target_value_vld,
                                       query_idx, query_valid,
                                       symbol_emb, value_emb,
                                       Wf1, bf1, Wf2, bf2,
                                       Wo1, bo1, Wo2, bo2, out);
}